// round 8
// baseline (speedup 1.0000x reference)
#include <cuda_runtime.h>
#include <cuda_bf16.h>

// Problem constants
#define NMAX 50000
#define D    128
#define G    512
#define H    64

// Scratch (static device globals — allowed; runtime alloc is not)
__device__ float g_hs [NMAX * D];   // (X@W) * dinv[row]
__device__ float g_agg[NMAX * D];   // accumulator (init = hs, i.e. self loop)
__device__ float g_act[NMAX * D];   // relu(dinv*agg + b)
__device__ float g_deg [NMAX];
__device__ float g_dinv[NMAX];
__device__ float g_pool[G * D];
__device__ float g_cnt [G];

// ---------------------------------------------------------------------------
// init: deg = 1 (self loop), pool = 0, cnt = 0
__global__ void init_kernel(int n) {
    int i = blockIdx.x * blockDim.x + threadIdx.x;
    if (i < n)      g_deg[i]  = 1.0f;
    if (i < G * D)  g_pool[i] = 0.0f;
    if (i < G)      g_cnt[i]  = 0.0f;
}

// deg[dst] += 1 per edge  (edge_index is INT32: jax coerces int64->int32)
__global__ void deg_kernel(const int* __restrict__ dst, int E) {
    int e = blockIdx.x * blockDim.x + threadIdx.x;
    if (e < E) atomicAdd(&g_deg[dst[e]], 1.0f);
}

__global__ void dinv_kernel(int n) {
    int i = blockIdx.x * blockDim.x + threadIdx.x;
    if (i < n) g_dinv[i] = rsqrtf(g_deg[i]);   // deg >= 1 always (self loop)
}

// ---------------------------------------------------------------------------
// SGEMM: g_hs = g_agg = (X @ W) * dinv[row]
// 128x128 tile per block, 256 threads, 8x8 per thread, K chunked by 32.
// use_act != 0 -> input is g_act (device symbol, resolved in device code).
__global__ void __launch_bounds__(256, 2)
gemm_scale_kernel(const float* __restrict__ Xin, const float* __restrict__ W,
                  int n, int use_act) {
    const float* X = use_act ? (const float*)g_act : Xin;

    __shared__ float Xs[32][132];   // [k][row] transposed, padded
    __shared__ float Ws[32][128];   // [k][col]

    const int tx = threadIdx.x & 15;        // 0..15 -> col tile
    const int ty = threadIdx.x >> 4;        // 0..15 -> row tile
    const int row0 = blockIdx.x * 128;

    float c[8][8];
#pragma unroll
    for (int i = 0; i < 8; i++)
#pragma unroll
        for (int j = 0; j < 8; j++) c[i][j] = 0.0f;

    for (int k0 = 0; k0 < 128; k0 += 32) {
        // load X chunk (128 rows x 32 k) transposed: 1024 float4
        for (int i = threadIdx.x; i < 1024; i += 256) {
            int r = i >> 3, q = i & 7;
            float4 v = make_float4(0.f, 0.f, 0.f, 0.f);
            if (row0 + r < n)
                v = *(const float4*)&X[(size_t)(row0 + r) * D + k0 + q * 4];
            Xs[q * 4 + 0][r] = v.x;
            Xs[q * 4 + 1][r] = v.y;
            Xs[q * 4 + 2][r] = v.z;
            Xs[q * 4 + 3][r] = v.w;
        }
        // load W chunk (32 k x 128 cols): 1024 float4, coalesced
        for (int i = threadIdx.x; i < 1024; i += 256) {
            int r = i >> 5, q = i & 31;
            *(float4*)&Ws[r][q * 4] = *(const float4*)&W[(size_t)(k0 + r) * D + q * 4];
        }
        __syncthreads();

#pragma unroll
        for (int kk = 0; kk < 32; kk++) {
            const float4* xp = (const float4*)&Xs[kk][ty * 8];
            const float4* wp = (const float4*)&Ws[kk][tx * 8];
            float4 a0 = xp[0], a1 = xp[1];
            float4 b0 = wp[0], b1 = wp[1];
            float a[8] = {a0.x, a0.y, a0.z, a0.w, a1.x, a1.y, a1.z, a1.w};
            float b[8] = {b0.x, b0.y, b0.z, b0.w, b1.x, b1.y, b1.z, b1.w};
#pragma unroll
            for (int i = 0; i < 8; i++)
#pragma unroll
                for (int j = 0; j < 8; j++) c[i][j] = fmaf(a[i], b[j], c[i][j]);
        }
        __syncthreads();
    }

#pragma unroll
    for (int i = 0; i < 8; i++) {
        int r = row0 + ty * 8 + i;
        if (r < n) {
            float s = g_dinv[r];
            float* hp = &g_hs [(size_t)r * D + tx * 8];
            float* ap = &g_agg[(size_t)r * D + tx * 8];
            float4 o0 = make_float4(c[i][0] * s, c[i][1] * s, c[i][2] * s, c[i][3] * s);
            float4 o1 = make_float4(c[i][4] * s, c[i][5] * s, c[i][6] * s, c[i][7] * s);
            *(float4*)&hp[0] = o0;  *(float4*)&hp[4] = o1;
            *(float4*)&ap[0] = o0;  *(float4*)&ap[4] = o1;
        }
    }
}

// ---------------------------------------------------------------------------
// Scatter: agg[dst] += hs[src]  (one warp per edge, v4 reduction atomics)
__global__ void scatter_kernel(const int* __restrict__ src,
                               const int* __restrict__ dst, int E) {
    int warp = (blockIdx.x * blockDim.x + threadIdx.x) >> 5;
    int lane = threadIdx.x & 31;
    if (warp >= E) return;
    int s = src[warp];
    int d = dst[warp];
    float4 v = *(const float4*)&g_hs[(size_t)s * D + lane * 4];
    float* p = &g_agg[(size_t)d * D + lane * 4];
    asm volatile("red.global.add.v4.f32 [%0], {%1,%2,%3,%4};"
                 :: "l"(p), "f"(v.x), "f"(v.y), "f"(v.z), "f"(v.w) : "memory");
}

// act = relu(dinv[row] * agg + b)
__global__ void act_kernel(const float* __restrict__ b, int n) {
    int i = blockIdx.x * blockDim.x + threadIdx.x;   // float4 index
    if (i >= n * (D / 4)) return;
    int r = i >> 5;            // D/4 = 32
    int q = i & 31;
    float s = g_dinv[r];
    float4 v = *(const float4*)&g_agg[(size_t)i * 4];
    float4 bb = *(const float4*)&b[q * 4];
    float4 o;
    o.x = fmaxf(fmaf(s, v.x, bb.x), 0.f);
    o.y = fmaxf(fmaf(s, v.y, bb.y), 0.f);
    o.z = fmaxf(fmaf(s, v.z, bb.z), 0.f);
    o.w = fmaxf(fmaf(s, v.w, bb.w), 0.f);
    *(float4*)&g_act[(size_t)i * 4] = o;
}

// ---------------------------------------------------------------------------
// pool: one warp per node, v4 reduction into g_pool[batch[i]]
__global__ void pool_kernel(const int* __restrict__ batch, int n) {
    int warp = (blockIdx.x * blockDim.x + threadIdx.x) >> 5;
    int lane = threadIdx.x & 31;
    if (warp >= n) return;
    int g = batch[warp];
    float4 v = *(const float4*)&g_act[(size_t)warp * D + lane * 4];
    float* p = &g_pool[(size_t)g * D + lane * 4];
    asm volatile("red.global.add.v4.f32 [%0], {%1,%2,%3,%4};"
                 :: "l"(p), "f"(v.x), "f"(v.y), "f"(v.z), "f"(v.w) : "memory");
    if (lane == 0) atomicAdd(&g_cnt[g], 1.0f);
}

// classifier: out[g] = relu(pooled @ Wc + bc) @ Wo + bo
__global__ void classifier_kernel(const float* __restrict__ Wc,
                                  const float* __restrict__ bc,
                                  const float* __restrict__ Wo,
                                  const float* __restrict__ bo,
                                  float* __restrict__ out) {
    __shared__ float sm[H];
    __shared__ float ps[D];
    int g = blockIdx.x;
    int j = threadIdx.x;            // 0..63
    float inv = 1.0f / fmaxf(g_cnt[g], 1.0f);
    // stage pooled row in smem
    ps[j]      = g_pool[g * D + j]      * inv;
    ps[j + 64] = g_pool[g * D + j + 64] * inv;
    __syncthreads();
    float acc = bc[j];
#pragma unroll 8
    for (int k = 0; k < D; k++) acc = fmaf(ps[k], Wc[k * H + j], acc);
    float z = fmaxf(acc, 0.f);
    sm[j] = z * Wo[j];
    __syncthreads();
    for (int s = 32; s > 0; s >>= 1) {
        if (j < s) sm[j] += sm[j + s];
        __syncthreads();
    }
    if (j == 0) out[g] = sm[0] + bo[0];
}

// ---------------------------------------------------------------------------
extern "C" void kernel_launch(void* const* d_in, const int* in_sizes, int n_in,
                              void* d_out, int out_size) {
    const float* x    = (const float*)d_in[0];
    const int*   ei   = (const int*)d_in[1];    // int32! (jax default x64 off)
    const int*   bat  = (const int*)d_in[2];    // int32!
    const float* W1   = (const float*)d_in[3];
    const float* b1   = (const float*)d_in[4];
    const float* W2   = (const float*)d_in[5];
    const float* b2   = (const float*)d_in[6];
    const float* W3   = (const float*)d_in[7];
    const float* b3   = (const float*)d_in[8];
    const float* Wc   = (const float*)d_in[9];
    const float* bc   = (const float*)d_in[10];
    const float* Wo   = (const float*)d_in[11];
    const float* bo   = (const float*)d_in[12];
    float* out = (float*)d_out;

    const int n = in_sizes[0] / D;        // 50000
    const int E = in_sizes[1] / 2;        // 800000
    const int* src = ei;
    const int* dst = ei + E;

    // degree / dinv / init
    {
        int tot = (G * D > n) ? G * D : n;
        init_kernel<<<(tot + 255) / 256, 256>>>(n);
        deg_kernel<<<(E + 255) / 256, 256>>>(dst, E);
        dinv_kernel<<<(n + 255) / 256, 256>>>(n);
    }

    const int gemm_blocks = (n + 127) / 128;
    const int scat_blocks = (E * 32 + 255) / 256;
    const int act_blocks  = (n * 32 + 255) / 256;

    const float* Ws[3] = {W1, W2, W3};
    const float* bs[3] = {b1, b2, b3};
    for (int l = 0; l < 3; l++) {
        // layer 0 reads harness input x; layers 1,2 read g_act via device-side
        // symbol selection (host never touches the __device__ symbol address).
        gemm_scale_kernel<<<gemm_blocks, 256>>>(x, Ws[l], n, l > 0 ? 1 : 0);
        scatter_kernel<<<scat_blocks, 256>>>(src, dst, E);
        act_kernel<<<act_blocks, 256>>>(bs[l], n);
    }

    pool_kernel<<<(n * 32 + 255) / 256, 256>>>(bat, n);
    classifier_kernel<<<G, H>>>(Wc, bc, Wo, bo, out);
}